// round 4
// baseline (speedup 1.0000x reference)
#include <cuda_runtime.h>

// Problem constants (fixed by the reference generator)
#define NGR   64
#define NPG   96
#define NODES (NGR*NPG)       // 6144
#define HID   64
#define INF   32
#define EF    16
#define DEG   8
#define EDGES (NODES*DEG)     // 49152
#define EPG   (NPG*DEG)       // 768
#define PAIRS (NODES*NPG)     // 589824

// ---------------- packed f32x2 helpers --------------------------------------
__device__ __forceinline__ unsigned long long dup2(float v) {
    unsigned long long r;
    asm("mov.b64 %0, {%1, %1};" : "=l"(r) : "f"(v));
    return r;
}
__device__ __forceinline__ void ffma2(unsigned long long& d, unsigned long long a, unsigned long long b) {
    asm("fma.rn.f32x2 %0, %1, %2, %0;" : "+l"(d) : "l"(a), "l"(b));
}
__device__ __forceinline__ void unpack2(float& lo, float& hi, unsigned long long v) {
    asm("mov.b64 {%0, %1}, %2;" : "=f"(lo), "=f"(hi) : "l"(v));
}

// ---------------- scratch (static device globals) ---------------------------
__device__ float g_WA[INF*HID];
__device__ float g_WB[INF*HID];
__device__ float g_WC[EF*HID];
__device__ float g_biasA[HID];
__device__ float g_biasB[HID];
__device__ float g_biasC[HID];
__device__ float g_vecA[NODES*HID];
__device__ float g_vecB[NODES*HID];
__device__ float g_Ce[(size_t)EDGES*HID];

// ---------------- K1: compose affine layers (1 block, 1024 thr) -------------
__global__ void prep_kernel(const float* __restrict__ W_atom, const float* __restrict__ b_atom,
                            const float* __restrict__ W_bond, const float* __restrict__ b_bond,
                            const float* __restrict__ W_node, const float* __restrict__ b_node,
                            const float* __restrict__ W_edge, const float* __restrict__ b_edge,
                            const float* __restrict__ W1,     const float* __restrict__ b1)
{
    __shared__ float M1[INF*HID];
    __shared__ float bn[HID];
    __shared__ float M2[EF*HID];
    __shared__ float be[HID];
    const int tid = threadIdx.x;

    for (int idx = tid; idx < INF*HID; idx += blockDim.x) {
        int r = idx >> 6, k = idx & 63;
        float s = 0.f;
        for (int j = 0; j < HID; j++) s = fmaf(W_atom[r*HID+j], W_node[j*HID+k], s);
        M1[idx] = s;
    }
    for (int idx = tid; idx < EF*HID; idx += blockDim.x) {
        int r = idx >> 6, k = idx & 63;
        float s = 0.f;
        for (int j = 0; j < HID; j++) s = fmaf(W_bond[r*HID+j], W_edge[j*HID+k], s);
        M2[idx] = s;
    }
    if (tid < HID) {
        float s = b_node[tid];
        for (int j = 0; j < HID; j++) s = fmaf(b_atom[j], W_node[j*HID+tid], s);
        bn[tid] = s;
        float t = b_edge[tid];
        for (int j = 0; j < HID; j++) t = fmaf(b_bond[j], W_edge[j*HID+tid], t);
        be[tid] = t;
    }
    __syncthreads();

    for (int idx = tid; idx < INF*HID; idx += blockDim.x) {
        int r = idx >> 6, k = idx & 63;
        float sa = 0.f, sb = 0.f;
        for (int j = 0; j < HID; j++) {
            float m = M1[r*HID+j];
            sa = fmaf(m, W1[j*HID + k], sa);
            sb = fmaf(m, W1[(64+j)*HID + k], sb);
        }
        g_WA[idx] = sa;
        g_WB[idx] = sb;
    }
    for (int idx = tid; idx < EF*HID; idx += blockDim.x) {
        int r = idx >> 6, k = idx & 63;
        float s = 0.f;
        for (int j = 0; j < HID; j++) s = fmaf(M2[r*HID+j], W1[(128+j)*HID + k], s);
        g_WC[idx] = s;
    }
    if (tid < HID) {
        int k = tid;
        float sa = b1[k], sb = 0.f, sc = 0.f;
        for (int j = 0; j < HID; j++) {
            sa = fmaf(bn[j], W1[j*HID + k], sa);
            sb = fmaf(bn[j], W1[(64+j)*HID + k], sb);
            sc = fmaf(be[j], W1[(128+j)*HID + k], sc);
        }
        g_biasA[k] = sa;
        g_biasB[k] = sb;
        g_biasC[k] = sc;
    }
}

// ---------------- K2: fused per-node + per-edge layer-1 partials -------------
// blocks [0, NODES/2): node work (2 nodes x 128 thr)
// blocks [NODES/2, ...): edge work (4 edges x 256 thr)
#define NODE_BLOCKS (NODES/2)
#define EDGE_BLOCKS (EDGES/4)
__global__ void encode_kernel(const float* __restrict__ x, const float* __restrict__ ea)
{
    if (blockIdx.x < NODE_BLOCKS) {
        __shared__ float xr[2][INF];
        int half = threadIdx.x >> 7;          // 0..1
        int t    = threadIdx.x & 127;
        int node = blockIdx.x*2 + half;
        if (t < INF) xr[half][t] = x[node*INF + t];
        __syncthreads();
        int k = t & 63;
        const float* W = (t < 64) ? g_WA : g_WB;
        float s = (t < 64) ? g_biasA[k] : g_biasB[k];
        #pragma unroll
        for (int f = 0; f < INF; f++) s = fmaf(xr[half][f], W[f*HID + k], s);
        if (t < 64) g_vecA[node*HID + k] = s;
        else        g_vecB[node*HID + k] = s;
    } else {
        __shared__ float er[4][EF];
        int b   = blockIdx.x - NODE_BLOCKS;
        int grp = threadIdx.x >> 6;
        int k   = threadIdx.x & 63;
        int e   = b * 4 + grp;
        if (k < EF) er[grp][k] = ea[e*EF + k];
        __syncthreads();
        float s = g_biasC[k];
        #pragma unroll
        for (int f = 0; f < EF; f++) s = fmaf(er[grp][f], g_WC[f*HID + k], s);
        g_Ce[(size_t)e*HID + k] = s;
    }
}

// ---------------- K3: fused pairwise MLP, f32x2 register-tiled GEMM ----------
#define W2PITCH 72
__global__ void __launch_bounds__(192, 3)
pair_kernel(const int* __restrict__ edge_index,
            const float* __restrict__ W2, const float* __restrict__ b2,
            const float* __restrict__ W3, const float* __restrict__ b3,
            float* __restrict__ out)
{
    extern __shared__ float s[];
    float* H0   = s;                         // [2][64][96]
    float* W2s  = s + 2*64*96;               // [64][72]
    float* Au_s = W2s + 64*W2PITCH;          // [2][64]
    float* W3s  = Au_s + 128;                // [64]
    float* b2s  = W3s + 64;                  // [64]
    long long* elist = (long long*)(b2s + 64);   // [2][96]
    int* ecount = (int*)(elist + 2*96);          // [2]

    const int tid = threadIdx.x;
    const int h   = tid / 96;
    const int lt  = tid - h*96;
    const int u   = blockIdx.x*2 + h;
    const int g   = u / NPG;
    const int lu  = u - g*NPG;
    float* H0h = H0 + h*64*96;
    long long* el = elist + h*96;

    if (lt == 0) ecount[h] = 0;
    for (int idx = tid; idx < 64*64; idx += 192) {
        int m = idx >> 6, k = idx & 63;
        W2s[m*W2PITCH + k] = W2[idx];
    }
    if (tid < 64) { W3s[tid] = W3[tid]; b2s[tid] = b2[tid]; }
    if (lt < 64) Au_s[h*64 + lt] = g_vecA[(size_t)u*HID + lt];
    __syncthreads();

    // gather this node's out-edges
    const int* srcA = edge_index;
    const int* dstA = edge_index + EDGES;
    for (int e = g*EPG + lt; e < (g+1)*EPG; e += 96) {
        if (srcA[e] == u) {
            int p = atomicAdd(&ecount[h], 1);
            if (p < 96) el[p] = ((long long)e << 32) | (unsigned)(dstA[e] - g*NPG);
        }
    }
    __syncthreads();
    const int ec = min(ecount[h], 96);
    if (lt == 0) {      // deterministic order
        for (int a = 1; a < ec; a++) {
            long long v = el[a]; int b = a - 1;
            while (b >= 0 && el[b] > v) { el[b+1] = el[b]; b--; }
            el[b+1] = v;
        }
    }
    __syncthreads();

    // build H0 column j = lt
    {
        const int j = lt;
        const float4* vB4 = (const float4*)(g_vecB + (size_t)(g*NPG)*HID);
        const float4* Ce4 = (const float4*)g_Ce;
        const float4* Au4 = (const float4*)(Au_s + h*64);
        #pragma unroll
        for (int m4 = 0; m4 < 16; m4++) {
            float4 v = vB4[j*16 + m4];
            for (int q = 0; q < ec; q++) {
                long long pk = el[q];
                if ((int)(pk & 0xffffffffLL) == j) {
                    float4 c = Ce4[(size_t)((int)(pk >> 32))*16 + m4];
                    v.x += c.x; v.y += c.y; v.z += c.z; v.w += c.w;
                }
            }
            float4 a = Au4[m4];
            v.x = fmaxf(v.x + a.x, 0.f);
            v.y = fmaxf(v.y + a.y, 0.f);
            v.z = fmaxf(v.z + a.z, 0.f);
            v.w = fmaxf(v.w + a.w, 0.f);
            int m = 4*m4;
            H0h[(m+0)*96 + j] = v.x;
            H0h[(m+1)*96 + j] = v.y;
            H0h[(m+2)*96 + j] = v.z;
            H0h[(m+3)*96 + j] = v.w;
        }
    }
    __syncthreads();

    // GEMM: thread (jt,kt) computes h1[jt*8..+8][kt*8..+8]
    // accumulators packed f32x2 along k: acc2[a][b2], b2 in {0..3}
    const int jt = lt >> 3;      // 0..11
    const int kt = lt & 7;       // 0..7
    unsigned long long acc2[8][4];
    #pragma unroll
    for (int a = 0; a < 8; a++)
        #pragma unroll
        for (int b = 0; b < 4; b++) acc2[a][b] = 0ULL;

    const float* Abase = H0h + jt*8;
    const float* Bbase = W2s + kt*8;
    #pragma unroll 4
    for (int m = 0; m < 64; m++) {
        float4 a0 = *(const float4*)(Abase + m*96);
        float4 a1 = *(const float4*)(Abase + m*96 + 4);
        ulonglong2 bb0 = *(const ulonglong2*)(Bbase + m*W2PITCH);
        ulonglong2 bb1 = *(const ulonglong2*)(Bbase + m*W2PITCH + 4);
        unsigned long long ad[8];
        ad[0] = dup2(a0.x); ad[1] = dup2(a0.y); ad[2] = dup2(a0.z); ad[3] = dup2(a0.w);
        ad[4] = dup2(a1.x); ad[5] = dup2(a1.y); ad[6] = dup2(a1.z); ad[7] = dup2(a1.w);
        #pragma unroll
        for (int a = 0; a < 8; a++) {
            ffma2(acc2[a][0], ad[a], bb0.x);
            ffma2(acc2[a][1], ad[a], bb0.y);
            ffma2(acc2[a][2], ad[a], bb1.x);
            ffma2(acc2[a][3], ad[a], bb1.y);
        }
    }

    // epilogue: relu(h1+b2)*W3 partial over this thread's 8 k's,
    // then butterfly-reduce over the 8 kt lanes (same warp), STG.128 write.
    float po[8];
    {
        const float* b2p = b2s + kt*8;
        const float* w3p = W3s + kt*8;
        float bb[8], ww[8];
        #pragma unroll
        for (int b = 0; b < 8; b++) { bb[b] = b2p[b]; ww[b] = w3p[b]; }
        #pragma unroll
        for (int a = 0; a < 8; a++) {
            float p = 0.f;
            #pragma unroll
            for (int b2i = 0; b2i < 4; b2i++) {
                float lo, hi;
                unpack2(lo, hi, acc2[a][b2i]);
                p = fmaf(fmaxf(lo + bb[2*b2i],   0.f), ww[2*b2i],   p);
                p = fmaf(fmaxf(hi + bb[2*b2i+1], 0.f), ww[2*b2i+1], p);
            }
            po[a] = p;
        }
    }
    #pragma unroll
    for (int ofs = 4; ofs > 0; ofs >>= 1)
        #pragma unroll
        for (int a = 0; a < 8; a++)
            po[a] += __shfl_xor_sync(0xffffffffu, po[a], ofs, 8);

    if (kt == 0) {
        float bias = b3[0];
        float4 o0 = make_float4(po[0]+bias, po[1]+bias, po[2]+bias, po[3]+bias);
        float4 o1 = make_float4(po[4]+bias, po[5]+bias, po[6]+bias, po[7]+bias);
        float* op = out + (size_t)g*(NPG*NPG) + (size_t)lu*NPG + jt*8;
        *(float4*)op       = o0;
        *(float4*)(op + 4) = o1;
    }
}

// ---------------- launch -----------------------------------------------------
extern "C" void kernel_launch(void* const* d_in, const int* in_sizes, int n_in,
                              void* d_out, int out_size)
{
    const float* x          = (const float*)d_in[0];
    const float* edge_attr  = (const float*)d_in[1];
    const int*   edge_index = (const int*)  d_in[2];

    int w = 6;
    if (n_in >= 6 && in_sizes[5] != 1) w = 5;
    if (n_in == 19) w = 5;
    const float* W_atom = (const float*)d_in[w+0];
    const float* b_atom = (const float*)d_in[w+1];
    const float* W_bond = (const float*)d_in[w+2];
    const float* b_bond = (const float*)d_in[w+3];
    const float* W_node = (const float*)d_in[w+4];
    const float* b_node = (const float*)d_in[w+5];
    const float* W_edge = (const float*)d_in[w+6];
    const float* b_edge = (const float*)d_in[w+7];
    const float* W1     = (const float*)d_in[w+8];
    const float* b1     = (const float*)d_in[w+9];
    const float* W2     = (const float*)d_in[w+10];
    const float* b2     = (const float*)d_in[w+11];
    const float* W3     = (const float*)d_in[w+12];
    const float* b3     = (const float*)d_in[w+13];

    const int smem_bytes = (2*64*96 + 64*W2PITCH + 128 + 64 + 64) * (int)sizeof(float)
                           + 2*96*(int)sizeof(long long) + 2*(int)sizeof(int);
    cudaFuncSetAttribute(pair_kernel, cudaFuncAttributeMaxDynamicSharedMemorySize, smem_bytes);

    prep_kernel<<<1, 1024>>>(W_atom, b_atom, W_bond, b_bond, W_node, b_node,
                             W_edge, b_edge, W1, b1);
    encode_kernel<<<NODE_BLOCKS + EDGE_BLOCKS, 256>>>(x, edge_attr);
    pair_kernel<<<NODES/2, 192, smem_bytes>>>(edge_index, W2, b2, W3, b3, (float*)d_out);
}

// round 5
// speedup vs baseline: 1.4832x; 1.4832x over previous
#include <cuda_runtime.h>

// Problem constants (fixed by the reference generator)
#define NGR   64
#define NPG   96
#define NODES (NGR*NPG)       // 6144
#define HID   64
#define INF   32
#define EF    16
#define DEG   8
#define EDGES (NODES*DEG)     // 49152
#define EPG   (NPG*DEG)       // 768
#define PAIRS (NODES*NPG)     // 589824

// ---------------- scratch (static device globals) ---------------------------
__device__ float g_M1[INF*HID];     // W_atom @ W_node
__device__ float g_M2[EF*HID];      // W_bond @ W_edge
__device__ float g_bn[HID];
__device__ float g_be[HID];
__device__ float g_WA[INF*HID];
__device__ float g_WB[INF*HID];
__device__ float g_WC[EF*HID];
__device__ float g_biasA[HID];
__device__ float g_biasB[HID];
__device__ float g_biasC[HID];
__device__ float g_vecA[NODES*HID];
__device__ float g_vecB[NODES*HID];
__device__ float g_Ce[(size_t)EDGES*HID];

// ---------------- K1a: first composition stage (parallel) -------------------
__global__ void prep1_kernel(const float* __restrict__ W_atom, const float* __restrict__ b_atom,
                             const float* __restrict__ W_bond, const float* __restrict__ b_bond,
                             const float* __restrict__ W_node, const float* __restrict__ b_node,
                             const float* __restrict__ W_edge, const float* __restrict__ b_edge)
{
    int i = blockIdx.x * blockDim.x + threadIdx.x;
    if (i < INF*HID) {
        int r = i >> 6, k = i & 63;
        float s = 0.f;
        #pragma unroll 8
        for (int j = 0; j < HID; j++) s = fmaf(W_atom[r*HID+j], W_node[j*HID+k], s);
        g_M1[i] = s;
    } else if (i < INF*HID + EF*HID) {
        int i2 = i - INF*HID;
        int r = i2 >> 6, k = i2 & 63;
        float s = 0.f;
        #pragma unroll 8
        for (int j = 0; j < HID; j++) s = fmaf(W_bond[r*HID+j], W_edge[j*HID+k], s);
        g_M2[i2] = s;
    } else if (i < INF*HID + EF*HID + HID) {
        int k = i - (INF*HID + EF*HID);
        float s = b_node[k];
        #pragma unroll 8
        for (int j = 0; j < HID; j++) s = fmaf(b_atom[j], W_node[j*HID+k], s);
        g_bn[k] = s;
    } else if (i < INF*HID + EF*HID + 2*HID) {
        int k = i - (INF*HID + EF*HID + HID);
        float s = b_edge[k];
        #pragma unroll 8
        for (int j = 0; j < HID; j++) s = fmaf(b_bond[j], W_edge[j*HID+k], s);
        g_be[k] = s;
    }
}

// ---------------- K1b: fold into W1 blocks (parallel) ------------------------
__global__ void prep2_kernel(const float* __restrict__ W1, const float* __restrict__ b1)
{
    int i = blockIdx.x * blockDim.x + threadIdx.x;
    if (i < INF*HID) {                       // g_WA
        int r = i >> 6, k = i & 63;
        float s = 0.f;
        #pragma unroll 8
        for (int j = 0; j < HID; j++) s = fmaf(g_M1[r*HID+j], W1[j*HID + k], s);
        g_WA[i] = s;
    } else if (i < 2*INF*HID) {              // g_WB
        int i2 = i - INF*HID;
        int r = i2 >> 6, k = i2 & 63;
        float s = 0.f;
        #pragma unroll 8
        for (int j = 0; j < HID; j++) s = fmaf(g_M1[r*HID+j], W1[(64+j)*HID + k], s);
        g_WB[i2] = s;
    } else if (i < 2*INF*HID + EF*HID) {     // g_WC
        int i2 = i - 2*INF*HID;
        int r = i2 >> 6, k = i2 & 63;
        float s = 0.f;
        #pragma unroll 8
        for (int j = 0; j < HID; j++) s = fmaf(g_M2[r*HID+j], W1[(128+j)*HID + k], s);
        g_WC[i2] = s;
    } else if (i < 2*INF*HID + EF*HID + HID) {
        int k = i - (2*INF*HID + EF*HID);
        float sa = b1[k], sb = 0.f, sc = 0.f;
        #pragma unroll 4
        for (int j = 0; j < HID; j++) {
            sa = fmaf(g_bn[j], W1[j*HID + k], sa);
            sb = fmaf(g_bn[j], W1[(64+j)*HID + k], sb);
            sc = fmaf(g_be[j], W1[(128+j)*HID + k], sc);
        }
        g_biasA[k] = sa;
        g_biasB[k] = sb;
        g_biasC[k] = sc;
    }
}

// ---------------- K2: fused per-node + per-edge layer-1 partials -------------
#define NODE_BLOCKS (NODES/2)
#define EDGE_BLOCKS (EDGES/4)
__global__ void encode_kernel(const float* __restrict__ x, const float* __restrict__ ea)
{
    if (blockIdx.x < NODE_BLOCKS) {
        __shared__ float xr[2][INF];
        int half = threadIdx.x >> 7;
        int t    = threadIdx.x & 127;
        int node = blockIdx.x*2 + half;
        if (t < INF) xr[half][t] = x[node*INF + t];
        __syncthreads();
        int k = t & 63;
        const float* W = (t < 64) ? g_WA : g_WB;
        float s = (t < 64) ? g_biasA[k] : g_biasB[k];
        #pragma unroll
        for (int f = 0; f < INF; f++) s = fmaf(xr[half][f], W[f*HID + k], s);
        if (t < 64) g_vecA[node*HID + k] = s;
        else        g_vecB[node*HID + k] = s;
    } else {
        __shared__ float er[4][EF];
        int b   = blockIdx.x - NODE_BLOCKS;
        int grp = threadIdx.x >> 6;
        int k   = threadIdx.x & 63;
        int e   = b * 4 + grp;
        if (k < EF) er[grp][k] = ea[e*EF + k];
        __syncthreads();
        float s = g_biasC[k];
        #pragma unroll
        for (int f = 0; f < EF; f++) s = fmaf(er[grp][f], g_WC[f*HID + k], s);
        g_Ce[(size_t)e*HID + k] = s;
    }
}

// ---------------- K3: fused pairwise MLP, register-tiled GEMM ---------------
#define W2PITCH 72

#define FMA4(acc, a, b) \
    acc.x = fmaf(a, b.x, acc.x); \
    acc.y = fmaf(a, b.y, acc.y); \
    acc.z = fmaf(a, b.z, acc.z); \
    acc.w = fmaf(a, b.w, acc.w);

__global__ void __launch_bounds__(192, 3)
pair_kernel(const int* __restrict__ edge_index,
            const float* __restrict__ W2, const float* __restrict__ b2,
            const float* __restrict__ W3, const float* __restrict__ b3,
            float* __restrict__ out)
{
    extern __shared__ float s[];
    float* H0   = s;                         // [2][64][96]
    float* W2s  = s + 2*64*96;               // [64][72]
    float* Au_s = W2s + 64*W2PITCH;          // [2][64]
    float* W3s  = Au_s + 128;                // [64]
    float* b2s  = W3s + 64;                  // [64]
    long long* elist = (long long*)(b2s + 64);   // [2][96]
    int* ecount = (int*)(elist + 2*96);          // [2]

    const int tid = threadIdx.x;
    const int h   = tid / 96;
    const int lt  = tid - h*96;
    const int u   = blockIdx.x*2 + h;
    const int g   = u / NPG;
    const int lu  = u - g*NPG;
    float* H0h = H0 + h*64*96;
    long long* el = elist + h*96;

    if (lt == 0) ecount[h] = 0;
    for (int idx = tid; idx < 64*64; idx += 192) {
        int m = idx >> 6, k = idx & 63;
        W2s[m*W2PITCH + k] = W2[idx];
    }
    if (tid < 64) { W3s[tid] = W3[tid]; b2s[tid] = b2[tid]; }
    if (lt < 64) Au_s[h*64 + lt] = g_vecA[(size_t)u*HID + lt];
    __syncthreads();

    // gather this node's out-edges
    const int* srcA = edge_index;
    const int* dstA = edge_index + EDGES;
    for (int e = g*EPG + lt; e < (g+1)*EPG; e += 96) {
        if (srcA[e] == u) {
            int p = atomicAdd(&ecount[h], 1);
            if (p < 96) el[p] = ((long long)e << 32) | (unsigned)(dstA[e] - g*NPG);
        }
    }
    __syncthreads();
    const int ec = min(ecount[h], 96);
    if (lt == 0) {      // deterministic order
        for (int a = 1; a < ec; a++) {
            long long v = el[a]; int b = a - 1;
            while (b >= 0 && el[b] > v) { el[b+1] = el[b]; b--; }
            el[b+1] = v;
        }
    }
    __syncthreads();

    // ---- build H0 column j = lt: scan edge list ONCE, then vector loop ----
    {
        const int j = lt;
        int e0 = -1, e1 = -1, nm = 0;
        for (int q = 0; q < ec; q++) {
            long long pk = el[q];
            if ((int)(pk & 0xffffffffLL) == j) {
                int e = (int)(pk >> 32);
                if (nm == 0) e0 = e; else if (nm == 1) e1 = e;
                nm++;
            }
        }
        const float4* vB4 = (const float4*)(g_vecB + (size_t)(g*NPG)*HID);
        const float4* Ce4 = (const float4*)g_Ce;
        const float4* Au4 = (const float4*)(Au_s + h*64);
        if (nm <= 2) {
            #pragma unroll 4
            for (int m4 = 0; m4 < 16; m4++) {
                float4 v = vB4[j*16 + m4];
                if (e0 >= 0) {
                    float4 c = Ce4[(size_t)e0*16 + m4];
                    v.x += c.x; v.y += c.y; v.z += c.z; v.w += c.w;
                }
                if (e1 >= 0) {
                    float4 c = Ce4[(size_t)e1*16 + m4];
                    v.x += c.x; v.y += c.y; v.z += c.z; v.w += c.w;
                }
                float4 a = Au4[m4];
                int m = 4*m4;
                H0h[(m+0)*96 + j] = fmaxf(v.x + a.x, 0.f);
                H0h[(m+1)*96 + j] = fmaxf(v.y + a.y, 0.f);
                H0h[(m+2)*96 + j] = fmaxf(v.z + a.z, 0.f);
                H0h[(m+3)*96 + j] = fmaxf(v.w + a.w, 0.f);
            }
        } else {
            // cold general path (more than 2 duplicate edges to this column)
            for (int m4 = 0; m4 < 16; m4++) {
                float4 v = vB4[j*16 + m4];
                for (int q = 0; q < ec; q++) {
                    long long pk = el[q];
                    if ((int)(pk & 0xffffffffLL) == j) {
                        float4 c = Ce4[(size_t)((int)(pk >> 32))*16 + m4];
                        v.x += c.x; v.y += c.y; v.z += c.z; v.w += c.w;
                    }
                }
                float4 a = Au4[m4];
                int m = 4*m4;
                H0h[(m+0)*96 + j] = fmaxf(v.x + a.x, 0.f);
                H0h[(m+1)*96 + j] = fmaxf(v.y + a.y, 0.f);
                H0h[(m+2)*96 + j] = fmaxf(v.z + a.z, 0.f);
                H0h[(m+3)*96 + j] = fmaxf(v.w + a.w, 0.f);
            }
        }
    }
    __syncthreads();

    // ---- GEMM: thread (jt,kt) computes h1[jt*8..+8][kt*8..+8] ----
    const int jt = lt >> 3;      // 0..11
    const int kt = lt & 7;       // 0..7
    float4 acc[8][2];
    #pragma unroll
    for (int a = 0; a < 8; a++) {
        acc[a][0] = make_float4(0.f, 0.f, 0.f, 0.f);
        acc[a][1] = make_float4(0.f, 0.f, 0.f, 0.f);
    }

    const float* Abase = H0h + jt*8;
    const float* Bbase = W2s + kt*8;
    #pragma unroll 4
    for (int m = 0; m < 64; m++) {
        float4 a0 = *(const float4*)(Abase + m*96);
        float4 a1 = *(const float4*)(Abase + m*96 + 4);
        float4 b0 = *(const float4*)(Bbase + m*W2PITCH);
        float4 b1 = *(const float4*)(Bbase + m*W2PITCH + 4);
        FMA4(acc[0][0], a0.x, b0); FMA4(acc[0][1], a0.x, b1);
        FMA4(acc[1][0], a0.y, b0); FMA4(acc[1][1], a0.y, b1);
        FMA4(acc[2][0], a0.z, b0); FMA4(acc[2][1], a0.z, b1);
        FMA4(acc[3][0], a0.w, b0); FMA4(acc[3][1], a0.w, b1);
        FMA4(acc[4][0], a1.x, b0); FMA4(acc[4][1], a1.x, b1);
        FMA4(acc[5][0], a1.y, b0); FMA4(acc[5][1], a1.y, b1);
        FMA4(acc[6][0], a1.z, b0); FMA4(acc[6][1], a1.z, b1);
        FMA4(acc[7][0], a1.w, b0); FMA4(acc[7][1], a1.w, b1);
    }

    // ---- epilogue: relu(h1+b2)*W3 partial, shuffle-reduce over kt lanes ----
    float po[8];
    {
        float4 bb0 = *(const float4*)(b2s + kt*8);
        float4 bb1 = *(const float4*)(b2s + kt*8 + 4);
        float4 ww0 = *(const float4*)(W3s + kt*8);
        float4 ww1 = *(const float4*)(W3s + kt*8 + 4);
        #pragma unroll
        for (int a = 0; a < 8; a++) {
            float p = 0.f;
            p = fmaf(fmaxf(acc[a][0].x + bb0.x, 0.f), ww0.x, p);
            p = fmaf(fmaxf(acc[a][0].y + bb0.y, 0.f), ww0.y, p);
            p = fmaf(fmaxf(acc[a][0].z + bb0.z, 0.f), ww0.z, p);
            p = fmaf(fmaxf(acc[a][0].w + bb0.w, 0.f), ww0.w, p);
            p = fmaf(fmaxf(acc[a][1].x + bb1.x, 0.f), ww1.x, p);
            p = fmaf(fmaxf(acc[a][1].y + bb1.y, 0.f), ww1.y, p);
            p = fmaf(fmaxf(acc[a][1].z + bb1.z, 0.f), ww1.z, p);
            p = fmaf(fmaxf(acc[a][1].w + bb1.w, 0.f), ww1.w, p);
            po[a] = p;
        }
    }
    #pragma unroll
    for (int ofs = 4; ofs > 0; ofs >>= 1)
        #pragma unroll
        for (int a = 0; a < 8; a++)
            po[a] += __shfl_xor_sync(0xffffffffu, po[a], ofs, 8);

    if (kt == 0) {
        float bias = b3[0];
        float4 o0 = make_float4(po[0]+bias, po[1]+bias, po[2]+bias, po[3]+bias);
        float4 o1 = make_float4(po[4]+bias, po[5]+bias, po[6]+bias, po[7]+bias);
        float* op = out + (size_t)g*(NPG*NPG) + (size_t)lu*NPG + jt*8;
        *(float4*)op       = o0;
        *(float4*)(op + 4) = o1;
    }
}

// ---------------- launch -----------------------------------------------------
extern "C" void kernel_launch(void* const* d_in, const int* in_sizes, int n_in,
                              void* d_out, int out_size)
{
    const float* x          = (const float*)d_in[0];
    const float* edge_attr  = (const float*)d_in[1];
    const int*   edge_index = (const int*)  d_in[2];

    int w = 6;
    if (n_in >= 6 && in_sizes[5] != 1) w = 5;
    if (n_in == 19) w = 5;
    const float* W_atom = (const float*)d_in[w+0];
    const float* b_atom = (const float*)d_in[w+1];
    const float* W_bond = (const float*)d_in[w+2];
    const float* b_bond = (const float*)d_in[w+3];
    const float* W_node = (const float*)d_in[w+4];
    const float* b_node = (const float*)d_in[w+5];
    const float* W_edge = (const float*)d_in[w+6];
    const float* b_edge = (const float*)d_in[w+7];
    const float* W1     = (const float*)d_in[w+8];
    const float* b1     = (const float*)d_in[w+9];
    const float* W2     = (const float*)d_in[w+10];
    const float* b2     = (const float*)d_in[w+11];
    const float* W3     = (const float*)d_in[w+12];
    const float* b3     = (const float*)d_in[w+13];

    const int smem_bytes = (2*64*96 + 64*W2PITCH + 128 + 64 + 64) * (int)sizeof(float)
                           + 2*96*(int)sizeof(long long) + 2*(int)sizeof(int);
    cudaFuncSetAttribute(pair_kernel, cudaFuncAttributeMaxDynamicSharedMemorySize, smem_bytes);

    const int P1 = INF*HID + EF*HID + 2*HID;            // 3200
    const int P2 = 2*INF*HID + EF*HID + HID;            // 5184
    prep1_kernel<<<(P1 + 255)/256, 256>>>(W_atom, b_atom, W_bond, b_bond,
                                          W_node, b_node, W_edge, b_edge);
    prep2_kernel<<<(P2 + 255)/256, 256>>>(W1, b1);
    encode_kernel<<<NODE_BLOCKS + EDGE_BLOCKS, 256>>>(x, edge_attr);
    pair_kernel<<<NODES/2, 192, smem_bytes>>>(edge_index, W2, b2, W3, b3, (float*)d_out);
}